// round 7
// baseline (speedup 1.0000x reference)
#include <cuda_runtime.h>
#include <cstdint>

#define NN 100000
#define EE 1600000
#define FD 128
#define GG 512
#define LL 3
#define TG 64
#define NB ((NN + 1023) / 1024)   /* 98 scan blocks */
#define MTILES ((NN + 127) / 128) /* 782 */

#define BK 32                      /* K-chunk */
#define PIT 36                     /* chunk pitch: conflict-free frags */
#define TPIT 132                   /* full-K pitch for A/T tile */
#define ABUF (128 * PIT)           /* 4608 floats per W chunk slot */
#define BUFSZ (2 * ABUF)           /* proj stage chunk (A+W) = 9216 floats */
#define R0FL (128 * TPIT)          /* 16896 floats: A/T tile */
#define FUSED_SMEM ((R0FL + 2 * ABUF) * 4)   /* 104448 B -> 2 CTA/SM */
#define PROJ_SMEM (2 * BUFSZ * 4)  /* 73728 B (T tile 67584 + batch ids fit) */

// ---------------- device scratch (no allocs allowed) ----------------
__device__ float g_ha[(size_t)NN * FD];   // ping
__device__ float g_hb[(size_t)NN * FD];   // pong
__device__ float g_wt[9 * FD * FD];       // pre-transposed weights [n][k], tf32-rounded
__device__ float g_pool[LL * GG * FD];
__device__ int   g_deg[NN];
__device__ int   g_rowptr[NN + 1];
__device__ int   g_cursor[NN];
__device__ int   g_bsum[NB];
__device__ int   g_boff[NB];
__device__ int   g_srcsorted[EE];
__device__ int   g_gstart[GG + 1];

__device__ __forceinline__ uint32_t smem_u32(const void* p) {
    uint32_t a;
    asm("{ .reg .u64 t; cvta.to.shared.u64 t, %1; cvt.u32.u64 %0, t; }" : "=r"(a) : "l"(p));
    return a;
}
__device__ __forceinline__ void cp16(uint32_t dst, const void* src) {
    asm volatile("cp.async.cg.shared.global [%0], [%1], 16;"
                 :: "r"(dst), "l"(src) : "memory");
}
__device__ __forceinline__ float f2tf32f(float f) {
    uint32_t r;
    asm("cvt.rna.tf32.f32 %0, %1;" : "=r"(r) : "f"(f));
    return __uint_as_float(r);
}
__device__ __forceinline__ void mma_tf32(float* c, const uint32_t* a, const uint32_t* b) {
    asm volatile(
        "mma.sync.aligned.m16n8k8.row.col.f32.tf32.tf32.f32 "
        "{%0,%1,%2,%3}, {%4,%5,%6,%7}, {%8,%9}, {%0,%1,%2,%3};"
        : "+f"(c[0]), "+f"(c[1]), "+f"(c[2]), "+f"(c[3])
        : "r"(a[0]), "r"(a[1]), "r"(a[2]), "r"(a[3]), "r"(b[0]), "r"(b[1]));
}

// ---------------- init / CSR build ----------------
__global__ void k_init_zero() {
    int i = blockIdx.x * 256 + threadIdx.x;
    if (i < NN) g_deg[i] = 0;
    if (i < LL * GG * FD) g_pool[i] = 0.f;
}
__global__ void k_hist(const int* __restrict__ dst) {
    int e = blockIdx.x * 256 + threadIdx.x;
    if (e < EE) atomicAdd(&g_deg[dst[e]], 1);
}
__global__ void k_scan1() {
    __shared__ int sh[1024];
    int i = blockIdx.x * 1024 + threadIdx.x;
    int v = (i < NN) ? g_deg[i] : 0;
    sh[threadIdx.x] = v;
    __syncthreads();
    for (int off = 1; off < 1024; off <<= 1) {
        int t = sh[threadIdx.x];
        int a = (threadIdx.x >= off) ? sh[threadIdx.x - off] : 0;
        __syncthreads();
        sh[threadIdx.x] = t + a;
        __syncthreads();
    }
    if (i < NN) g_rowptr[i + 1] = sh[threadIdx.x];
    if (threadIdx.x == 1023) g_bsum[blockIdx.x] = sh[1023];
}
__global__ void k_scan2() {
    __shared__ int sh[128];
    int t = threadIdx.x;
    int v = (t < NB) ? g_bsum[t] : 0;
    sh[t] = v;
    __syncthreads();
    for (int off = 1; off < 128; off <<= 1) {
        int x = sh[t];
        int a = (t >= off) ? sh[t - off] : 0;
        __syncthreads();
        sh[t] = x + a;
        __syncthreads();
    }
    if (t < NB) g_boff[t] = sh[t] - v;
}
__global__ void k_scan3() {
    int i = blockIdx.x * 1024 + threadIdx.x;
    if (i < NN) g_rowptr[i + 1] += g_boff[blockIdx.x];
    if (i == 0) g_rowptr[0] = 0;
}
__global__ void k_copycur() {
    int i = blockIdx.x * 256 + threadIdx.x;
    if (i < NN) g_cursor[i] = g_rowptr[i];
}
__global__ void k_bucket(const int* __restrict__ src, const int* __restrict__ dst) {
    int e = blockIdx.x * 256 + threadIdx.x;
    if (e < EE) {
        int d = dst[e];
        int pos = atomicAdd(&g_cursor[d], 1);
        g_srcsorted[pos] = src[e];
    }
}
__global__ void k_gstart(const int* __restrict__ batch) {
    int g = blockIdx.x * 256 + threadIdx.x;
    if (g <= GG) {
        int lo = 0, hi = NN;
        while (lo < hi) {
            int mid = (lo + hi) >> 1;
            if (batch[mid] < g) lo = mid + 1; else hi = mid;
        }
        g_gstart[g] = lo;
    }
}

// ---------------- weight transpose + tf32 rna rounding ----------------
__global__ void k_wtrans(const float* __restrict__ w1, const float* __restrict__ w2,
                         const float* __restrict__ w3) {
    __shared__ float t[32][33];
    int mi = blockIdx.z;
    const float* src = (mi < 3) ? (w1 + (size_t)mi * FD * FD)
                     : (mi < 6) ? (w2 + (size_t)(mi - 3) * FD * FD)
                                : (w3 + (size_t)(mi - 6) * FD * FD);
    float* dst = g_wt + (size_t)mi * FD * FD;
    int x0 = blockIdx.x * 32, y0 = blockIdx.y * 32;
    for (int dy = threadIdx.y; dy < 32; dy += 8)
        t[dy][threadIdx.x] = src[(size_t)(y0 + dy) * FD + x0 + threadIdx.x];
    __syncthreads();
    for (int dy = threadIdx.y; dy < 32; dy += 8)
        dst[(size_t)(x0 + dy) * FD + y0 + threadIdx.x] = f2tf32f(t[threadIdx.x][dy]);
}

// ---------------- fused gather + GIN MLP ----------------
// Reads h (input buffer), writes C (DIFFERENT buffer — ping-pong, no race).
// A_row = rna((1+eps)h[m] + sum_{src} h[src]) gathered into SMEM;
// H = relu(A@W1^T + b1) @ W2^T + b2.  W1/W2 share one cp.async double buffer.
__global__ void __launch_bounds__(256, 2) k_gin_mlp(
    const float* __restrict__ h, const float* __restrict__ epsp,
    const float* __restrict__ W1t, const float* __restrict__ b1p,
    const float* __restrict__ W2t, const float* __restrict__ b2p,
    float* __restrict__ C, int M)
{
    extern __shared__ float smem[];
    uint32_t sb = smem_u32(smem);
    uint32_t wb = sb + R0FL * 4;
    float* wbuf = smem + R0FL;

    int tid = threadIdx.x;
    int w = tid >> 5, lane = tid & 31;
    int m0 = blockIdx.x * 128;

    auto stageW = [&](const float* W, int c, int slot) {
#pragma unroll
        for (int i = 0; i < 4; i++) {
            int o = i * 256 + tid;
            int row = o >> 3;
            int q = o & 7;
            cp16(wb + (uint32_t)(slot * (ABUF * 4) + row * (PIT * 4) + q * 16),
                 W + (size_t)row * FD + c * BK + q * 4);
        }
        asm volatile("cp.async.commit_group;" ::: "memory");
    };

    stageW(W1t, 0, 0);   // g0
    stageW(W1t, 1, 1);   // g1

    // ---- gather A rows into R0 (overlapped with W1 prefetch) ----
    {
        float alpha = 1.0f + epsp[0];
        const float4* hp = (const float4*)h;
#pragma unroll 1
        for (int i = 0; i < 16; i++) {
            int r = w * 16 + i;
            int node = m0 + r;
            float4 acc = make_float4(0.f, 0.f, 0.f, 0.f);
            if (node < M) {
                float4 hv = hp[(size_t)node * 32 + lane];
                acc.x = alpha * hv.x; acc.y = alpha * hv.y;
                acc.z = alpha * hv.z; acc.w = alpha * hv.w;
                int s = g_rowptr[node], e = g_rowptr[node + 1];
                int j = s;
                for (; j + 1 < e; j += 2) {
                    int s0 = g_srcsorted[j], s1 = g_srcsorted[j + 1];
                    float4 v0 = hp[(size_t)s0 * 32 + lane];
                    float4 v1 = hp[(size_t)s1 * 32 + lane];
                    acc.x += v0.x + v1.x; acc.y += v0.y + v1.y;
                    acc.z += v0.z + v1.z; acc.w += v0.w + v1.w;
                }
                if (j < e) {
                    int s0 = g_srcsorted[j];
                    float4 v0 = hp[(size_t)s0 * 32 + lane];
                    acc.x += v0.x; acc.y += v0.y; acc.z += v0.z; acc.w += v0.w;
                }
            }
            acc.x = f2tf32f(acc.x); acc.y = f2tf32f(acc.y);
            acc.z = f2tf32f(acc.z); acc.w = f2tf32f(acc.w);
            ((float4*)(smem + r * TPIT))[lane] = acc;
        }
    }
    __syncthreads();

    int warpM = w >> 2, warpN = w & 3;
    int g = lane >> 2, t = lane & 3;

    float c[4][4][4];
#pragma unroll
    for (int ma = 0; ma < 4; ma++)
#pragma unroll
        for (int nb = 0; nb < 4; nb++)
#pragma unroll
            for (int r = 0; r < 4; r++) c[ma][nb][r] = 0.f;

    const uint32_t* Ts = (const uint32_t*)smem;

    auto chunk_mma = [&](int ch, int slot) {
        const uint32_t* Bs = (const uint32_t*)(wbuf + slot * ABUF);
#pragma unroll
        for (int ks = 0; ks < 4; ks++) {
            int k0 = ch * 32 + ks * 8;
            uint32_t af[4][4];
#pragma unroll
            for (int ma = 0; ma < 4; ma++) {
                int r = warpM * 64 + ma * 16 + g;
                const uint32_t* ap = Ts + r * TPIT + k0 + t;
                af[ma][0] = ap[0];
                af[ma][1] = ap[8 * TPIT];
                af[ma][2] = ap[4];
                af[ma][3] = ap[8 * TPIT + 4];
            }
            uint32_t bf[4][2];
#pragma unroll
            for (int nb = 0; nb < 4; nb++) {
                int n = warpN * 32 + nb * 8 + g;
                const uint32_t* bp = Bs + n * PIT + ks * 8 + t;
                bf[nb][0] = bp[0];
                bf[nb][1] = bp[4];
            }
#pragma unroll
            for (int ma = 0; ma < 4; ma++)
#pragma unroll
                for (int nb = 0; nb < 4; nb++)
                    mma_tf32(c[ma][nb], af[ma], bf[nb]);
        }
    };

    // ---- stage 1: T_acc = A @ W1^T ----
#pragma unroll
    for (int ch = 0; ch < 4; ch++) {
        asm volatile("cp.async.wait_group 1;" ::: "memory");
        __syncthreads();
        chunk_mma(ch, ch & 1);
        __syncthreads();
        if (ch < 2) stageW(W1t, ch + 2, ch & 1);        // g2, g3
        else        stageW(W2t, ch - 2, ch & 1);        // g4, g5
    }

    // ---- T = rna(relu(T_acc + b1)) overwrites A in R0 ----
#pragma unroll
    for (int ma = 0; ma < 4; ma++) {
        int r0 = warpM * 64 + ma * 16 + g;
#pragma unroll
        for (int nb = 0; nb < 4; nb++) {
            int cn = warpN * 32 + nb * 8 + 2 * t;
            float b0 = b1p[cn], b1v = b1p[cn + 1];
            smem[r0 * TPIT + cn]           = f2tf32f(fmaxf(c[ma][nb][0] + b0, 0.f));
            smem[r0 * TPIT + cn + 1]       = f2tf32f(fmaxf(c[ma][nb][1] + b1v, 0.f));
            smem[(r0 + 8) * TPIT + cn]     = f2tf32f(fmaxf(c[ma][nb][2] + b0, 0.f));
            smem[(r0 + 8) * TPIT + cn + 1] = f2tf32f(fmaxf(c[ma][nb][3] + b1v, 0.f));
#pragma unroll
            for (int r = 0; r < 4; r++) c[ma][nb][r] = 0.f;
        }
    }
    __syncthreads();

    // ---- stage 2: H_acc = T @ W2^T ----
#pragma unroll
    for (int ch = 0; ch < 4; ch++) {
        if (ch < 3) asm volatile("cp.async.wait_group 1;" ::: "memory");
        else        asm volatile("cp.async.wait_group 0;" ::: "memory");
        __syncthreads();
        chunk_mma(ch, ch & 1);
        __syncthreads();
        if (ch < 2) stageW(W2t, ch + 2, ch & 1);        // g6, g7
    }

    // ---- epilogue: H = acc + b2 (raw fp32; gnorm rounds later) ----
#pragma unroll
    for (int ma = 0; ma < 4; ma++) {
        int r0 = m0 + warpM * 64 + ma * 16 + g;
#pragma unroll
        for (int nb = 0; nb < 4; nb++) {
            int cn = warpN * 32 + nb * 8 + 2 * t;
            float b0 = b2p[cn], b1v = b2p[cn + 1];
            if (r0 < M)
                *(float2*)&C[(size_t)r0 * FD + cn] =
                    make_float2(c[ma][nb][0] + b0, c[ma][nb][1] + b1v);
            if (r0 + 8 < M)
                *(float2*)&C[(size_t)(r0 + 8) * FD + cn] =
                    make_float2(c[ma][nb][2] + b0, c[ma][nb][3] + b1v);
        }
    }
}

// ---------------- proj GEMM fused with pool partial-sums ----------------
// T = relu(h @ W1p^T + b1p) kept in SMEM; per-graph column sums atomicAdd'ed into poolp.
__global__ void __launch_bounds__(256) k_gemm_proj(
    const float* __restrict__ A,
    const float* __restrict__ Wt, const float* __restrict__ bias,
    const int* __restrict__ batch, float* __restrict__ poolp, int M)
{
    extern __shared__ float smem[];
    uint32_t sb = smem_u32(smem);
    int* sbatch = (int*)(smem + R0FL);   // 128 ints, fits in PROJ_SMEM spare

    int tid = threadIdx.x;
    int w = tid >> 5, lane = tid & 31;
    int m0 = blockIdx.x * 128;

    auto stage = [&](int c, int buf) {
        uint32_t base = sb + (uint32_t)buf * (BUFSZ * 4);
#pragma unroll
        for (int i = 0; i < 8; i++) {
            int o = i * 256 + tid;
            int row = (o & 1023) >> 3;
            int q = o & 7;
            uint32_t dst = base + (uint32_t)((o >> 10) * (ABUF * 4) + row * (PIT * 4) + q * 16);
            if (o < 1024) {
                int m = m0 + row;
                cp16(dst, A + ((m < M) ? ((size_t)m * FD + c * BK + q * 4)
                                       : ((size_t)c * BK + q * 4)));
            } else {
                cp16(dst, Wt + (size_t)row * FD + c * BK + q * 4);
            }
        }
        asm volatile("cp.async.commit_group;" ::: "memory");
    };

    stage(0, 0);

    int warpM = w >> 2, warpN = w & 3;
    int g = lane >> 2, t = lane & 3;

    float c[4][4][4];
#pragma unroll
    for (int ma = 0; ma < 4; ma++)
#pragma unroll
        for (int nb = 0; nb < 4; nb++)
#pragma unroll
            for (int r = 0; r < 4; r++) c[ma][nb][r] = 0.f;

#pragma unroll
    for (int ch = 0; ch < 4; ch++) {
        if (ch < 3) stage(ch + 1, (ch + 1) & 1);
        if (ch < 3)
            asm volatile("cp.async.wait_group 1;" ::: "memory");
        else
            asm volatile("cp.async.wait_group 0;" ::: "memory");
        __syncthreads();

        const uint32_t* As = (const uint32_t*)(smem + (ch & 1) * BUFSZ);
        const uint32_t* Bs = As + ABUF;
#pragma unroll
        for (int ks = 0; ks < 4; ks++) {
            int k0 = ks * 8;
            uint32_t af[4][4];
#pragma unroll
            for (int ma = 0; ma < 4; ma++) {
                int r = warpM * 64 + ma * 16 + g;
                const uint32_t* ap = As + r * PIT + k0 + t;
                af[ma][0] = ap[0];
                af[ma][1] = ap[8 * PIT];
                af[ma][2] = ap[4];
                af[ma][3] = ap[8 * PIT + 4];
            }
            uint32_t bf[4][2];
#pragma unroll
            for (int nb = 0; nb < 4; nb++) {
                int n = warpN * 32 + nb * 8 + g;
                const uint32_t* bp = Bs + n * PIT + k0 + t;
                bf[nb][0] = bp[0];
                bf[nb][1] = bp[4];
            }
#pragma unroll
            for (int ma = 0; ma < 4; ma++)
#pragma unroll
                for (int nb = 0; nb < 4; nb++)
                    mma_tf32(c[ma][nb], af[ma], bf[nb]);
        }
        __syncthreads();
    }

    // ---- T = relu(acc + b1) into SMEM [128][TPIT]; batch ids alongside ----
    if (tid < 128) sbatch[tid] = (m0 + tid < M) ? batch[m0 + tid] : -1;
#pragma unroll
    for (int ma = 0; ma < 4; ma++) {
        int r0 = warpM * 64 + ma * 16 + g;
#pragma unroll
        for (int nb = 0; nb < 4; nb++) {
            int cn = warpN * 32 + nb * 8 + 2 * t;
            float b0 = bias[cn], b1v = bias[cn + 1];
            smem[r0 * TPIT + cn]           = fmaxf(c[ma][nb][0] + b0, 0.f);
            smem[r0 * TPIT + cn + 1]       = fmaxf(c[ma][nb][1] + b1v, 0.f);
            smem[(r0 + 8) * TPIT + cn]     = fmaxf(c[ma][nb][2] + b0, 0.f);
            smem[(r0 + 8) * TPIT + cn + 1] = fmaxf(c[ma][nb][3] + b1v, 0.f);
        }
    }
    __syncthreads();

    // ---- segmented column sums: thread (half, f) scans 64 rows ----
    {
        int f = tid & 127;
        int half = tid >> 7;
        int base = half * 64;
        if (m0 + base < M) {
            float acc = 0.f;
            int curg = sbatch[base];
            for (int i = 0; i < 64; i++) {
                int gi = sbatch[base + i];
                if (gi < 0) break;
                if (gi != curg) {
                    atomicAdd(&poolp[(size_t)curg * FD + f], acc);
                    acc = 0.f;
                    curg = gi;
                }
                acc += smem[(base + i) * TPIT + f];
            }
            if (curg >= 0) atomicAdd(&poolp[(size_t)curg * FD + f], acc);
        }
    }
}

// ---------------- GraphNorm (+relu), output tf32-rounded ----------------
__global__ void __launch_bounds__(128) k_gnorm(
    float* __restrict__ h,
    const float* __restrict__ scale, const float* __restrict__ weight,
    const float* __restrict__ bias)
{
    int g = blockIdx.x;
    int f = threadIdx.x;
    int s = g_gstart[g], e = g_gstart[g + 1];
    float cnt = fmaxf((float)(e - s), 1.0f);

    float sum = 0.f;
#pragma unroll 4
    for (int i = s; i < e; i++) sum += h[(size_t)i * FD + f];
    float ms = (sum / cnt) * scale[f];

    float v = 0.f;
#pragma unroll 4
    for (int i = s; i < e; i++) {
        float d = h[(size_t)i * FD + f] - ms;
        v += d * d;
    }
    float inv = weight[f] * rsqrtf(v / cnt + 1e-8f);
    float bf = bias[f];

#pragma unroll 4
    for (int i = s; i < e; i++) {
        float d = h[(size_t)i * FD + f] - ms;
        h[(size_t)i * FD + f] = f2tf32f(fmaxf(inv * d + bf, 0.f));
    }
}

// ---------------- final tiny GEMM: out[g, lofs+f] = pool[g]@W2 + cnt*b2 ----------------
__global__ void __launch_bounds__(128) k_pool2(
    const float* __restrict__ poolp,
    const float* __restrict__ w2, const float* __restrict__ b2,
    float* __restrict__ out, int lofs)
{
    __shared__ float sp[128];
    int g = blockIdx.x;
    int f = threadIdx.x;
    sp[f] = poolp[(size_t)g * FD + f];
    __syncthreads();
    if (f < TG) {
        int cnt = g_gstart[g + 1] - g_gstart[g];
        float o = (float)cnt * b2[f];
#pragma unroll 8
        for (int k = 0; k < FD; k++) o += sp[k] * w2[k * TG + f];
        out[(size_t)g * (LL * TG) + lofs + f] = o;
    }
}

// ---------------- launcher ----------------
extern "C" void kernel_launch(void* const* d_in, const int* in_sizes, int n_in,
                              void* d_out, int out_size) {
    const float* x        = (const float*)d_in[0];
    const int*   edge     = (const int*)d_in[1];
    const int*   batch    = (const int*)d_in[2];
    const float* conv_w1  = (const float*)d_in[3];
    const float* conv_b1  = (const float*)d_in[4];
    const float* conv_w2  = (const float*)d_in[5];
    const float* conv_b2  = (const float*)d_in[6];
    const float* eps      = (const float*)d_in[7];
    const float* gn_scale = (const float*)d_in[8];
    const float* gn_weight= (const float*)d_in[9];
    const float* gn_bias  = (const float*)d_in[10];
    const float* proj_w1  = (const float*)d_in[11];
    const float* proj_b1  = (const float*)d_in[12];
    const float* proj_w2  = (const float*)d_in[13];
    const float* proj_b2  = (const float*)d_in[14];
    float* out = (float*)d_out;

    const int* src = edge;
    const int* dst = edge + EE;

    float *p_ha, *p_hb, *p_wt, *p_pool;
    cudaGetSymbolAddress((void**)&p_ha, g_ha);
    cudaGetSymbolAddress((void**)&p_hb, g_hb);
    cudaGetSymbolAddress((void**)&p_wt, g_wt);
    cudaGetSymbolAddress((void**)&p_pool, g_pool);

    cudaFuncSetAttribute(k_gin_mlp, cudaFuncAttributeMaxDynamicSharedMemorySize, FUSED_SMEM);
    cudaFuncSetAttribute(k_gemm_proj, cudaFuncAttributeMaxDynamicSharedMemorySize, PROJ_SMEM);

    // init + CSR build + graph starts + weight transpose (tf32-rounded)
    k_init_zero<<<(LL * GG * FD + 255) / 256, 256>>>();
    k_hist<<<(EE + 255) / 256, 256>>>(dst);
    k_scan1<<<NB, 1024>>>();
    k_scan2<<<1, 128>>>();
    k_scan3<<<NB, 1024>>>();
    k_copycur<<<(NN + 255) / 256, 256>>>();
    k_bucket<<<(EE + 255) / 256, 256>>>(src, dst);
    k_gstart<<<3, 256>>>(batch);
    k_wtrans<<<dim3(4, 4, 9), dim3(32, 8)>>>(conv_w1, conv_w2, proj_w1);

    const float* hin = x;
    float* hout = p_ha;
    for (int l = 0; l < LL; l++) {
        // hout = relu(gather(hin)@W1 + b1)@W2 + b2   (ping-pong: hin != hout)
        k_gin_mlp<<<MTILES, 256, FUSED_SMEM>>>(hin, eps + l,
                                               p_wt + (size_t)l * FD * FD,
                                               conv_b1 + (size_t)l * FD,
                                               p_wt + (size_t)(3 + l) * FD * FD,
                                               conv_b2 + (size_t)l * FD, hout, NN);
        // GraphNorm + relu + rna (in place on hout; block-per-graph owns its rows)
        k_gnorm<<<GG, 128>>>(hout, gn_scale + (size_t)l * FD,
                             gn_weight + (size_t)l * FD, gn_bias + (size_t)l * FD);
        // pool_l += segsum(relu(hout@W1p + b1p))
        k_gemm_proj<<<MTILES, 256, PROJ_SMEM>>>(hout,
                                                p_wt + (size_t)(6 + l) * FD * FD,
                                                proj_b1 + (size_t)l * FD,
                                                batch, p_pool + (size_t)l * GG * FD, NN);
        // out_l = pool_l @ W2p + cnt*b2p
        k_pool2<<<GG, 128>>>(p_pool + (size_t)l * GG * FD,
                             proj_w2 + (size_t)l * FD * TG,
                             proj_b2 + (size_t)l * TG, out, l * TG);
        hin = hout;
        hout = (hout == p_ha) ? p_hb : p_ha;
    }
}

// round 8
// speedup vs baseline: 1.1382x; 1.1382x over previous
#include <cuda_runtime.h>
#include <cuda_fp16.h>
#include <cstdint>

#define NN 100000
#define EE 1600000
#define FD 128
#define GG 512
#define LL 3
#define TG 64
#define NB ((NN + 1023) / 1024)   /* 98 scan blocks */
#define MTILES ((NN + 127) / 128) /* 782 */

#define BK 32                      /* K-chunk */
#define PIT 36                     /* chunk pitch: conflict-free frags */
#define TPIT 132                   /* full-K pitch for proj T tile */
#define ABUF (128 * PIT)           /* 4608 floats per chunk operand */
#define BUFSZ (2 * ABUF)           /* stage chunk (A+W) = 9216 floats */
#define R0FL (128 * TPIT)          /* 16896 floats (proj T tile) */
#define GEMM_SMEM (2 * BUFSZ * 4)  /* 73728 B double-buffered */

// ---------------- device scratch (no allocs allowed) ----------------
__device__ float  g_h[(size_t)NN * FD];
__device__ __half g_h16[(size_t)NN * FD];   // fp16 gather source
__device__ float  g_aggr[(size_t)NN * FD];
__device__ float  g_t[(size_t)NN * FD];
__device__ float  g_wt[9 * FD * FD];        // pre-transposed weights [n][k], tf32-rounded
__device__ float  g_pool[LL * GG * FD];
__device__ int    g_deg[NN];
__device__ int    g_rowptr[NN + 1];
__device__ int    g_cursor[NN];
__device__ int    g_bsum[NB];
__device__ int    g_boff[NB];
__device__ int    g_srcsorted[EE];
__device__ int    g_gstart[GG + 1];

__device__ __forceinline__ uint32_t smem_u32(const void* p) {
    uint32_t a;
    asm("{ .reg .u64 t; cvta.to.shared.u64 t, %1; cvt.u32.u64 %0, t; }" : "=r"(a) : "l"(p));
    return a;
}
__device__ __forceinline__ void cp16(uint32_t dst, const void* src) {
    asm volatile("cp.async.cg.shared.global [%0], [%1], 16;"
                 :: "r"(dst), "l"(src) : "memory");
}
__device__ __forceinline__ float f2tf32f(float f) {
    uint32_t r;
    asm("cvt.rna.tf32.f32 %0, %1;" : "=r"(r) : "f"(f));
    return __uint_as_float(r);
}
__device__ __forceinline__ void mma_tf32(float* c, const uint32_t* a, const uint32_t* b) {
    asm volatile(
        "mma.sync.aligned.m16n8k8.row.col.f32.tf32.tf32.f32 "
        "{%0,%1,%2,%3}, {%4,%5,%6,%7}, {%8,%9}, {%0,%1,%2,%3};"
        : "+f"(c[0]), "+f"(c[1]), "+f"(c[2]), "+f"(c[3])
        : "r"(a[0]), "r"(a[1]), "r"(a[2]), "r"(a[3]), "r"(b[0]), "r"(b[1]));
}
__device__ __forceinline__ void acc_h4(float4& acc, uint2 v) {
    float2 f0 = __half22float2(*(const __half2*)&v.x);
    float2 f1 = __half22float2(*(const __half2*)&v.y);
    acc.x += f0.x; acc.y += f0.y; acc.z += f1.x; acc.w += f1.y;
}

// ---------------- init / CSR build ----------------
__global__ void k_init_zero() {
    int i = blockIdx.x * 256 + threadIdx.x;
    if (i < NN) g_deg[i] = 0;
    if (i < LL * GG * FD) g_pool[i] = 0.f;
}
__global__ void k_hist(const int* __restrict__ dst) {
    int e = blockIdx.x * 256 + threadIdx.x;
    if (e < EE) atomicAdd(&g_deg[dst[e]], 1);
}
__global__ void k_scan1() {
    __shared__ int sh[1024];
    int i = blockIdx.x * 1024 + threadIdx.x;
    int v = (i < NN) ? g_deg[i] : 0;
    sh[threadIdx.x] = v;
    __syncthreads();
    for (int off = 1; off < 1024; off <<= 1) {
        int t = sh[threadIdx.x];
        int a = (threadIdx.x >= off) ? sh[threadIdx.x - off] : 0;
        __syncthreads();
        sh[threadIdx.x] = t + a;
        __syncthreads();
    }
    if (i < NN) g_rowptr[i + 1] = sh[threadIdx.x];
    if (threadIdx.x == 1023) g_bsum[blockIdx.x] = sh[1023];
}
__global__ void k_scan2() {
    __shared__ int sh[128];
    int t = threadIdx.x;
    int v = (t < NB) ? g_bsum[t] : 0;
    sh[t] = v;
    __syncthreads();
    for (int off = 1; off < 128; off <<= 1) {
        int x = sh[t];
        int a = (t >= off) ? sh[t - off] : 0;
        __syncthreads();
        sh[t] = x + a;
        __syncthreads();
    }
    if (t < NB) g_boff[t] = sh[t] - v;
}
__global__ void k_scan3() {
    int i = blockIdx.x * 1024 + threadIdx.x;
    if (i < NN) g_rowptr[i + 1] += g_boff[blockIdx.x];
    if (i == 0) g_rowptr[0] = 0;
}
__global__ void k_copycur() {
    int i = blockIdx.x * 256 + threadIdx.x;
    if (i < NN) g_cursor[i] = g_rowptr[i];
}
__global__ void k_bucket(const int* __restrict__ src, const int* __restrict__ dst) {
    int e = blockIdx.x * 256 + threadIdx.x;
    if (e < EE) {
        int d = dst[e];
        int pos = atomicAdd(&g_cursor[d], 1);
        g_srcsorted[pos] = src[e];
    }
}
__global__ void k_gstart(const int* __restrict__ batch) {
    int g = blockIdx.x * 256 + threadIdx.x;
    if (g <= GG) {
        int lo = 0, hi = NN;
        while (lo < hi) {
            int mid = (lo + hi) >> 1;
            if (batch[mid] < g) lo = mid + 1; else hi = mid;
        }
        g_gstart[g] = lo;
    }
}

// ---------------- x -> fp16 convert ----------------
__global__ void k_x16(const float* __restrict__ x) {
    int i = blockIdx.x * 256 + threadIdx.x;      // half2 index
    if (i < NN * FD / 2) {
        float2 v = ((const float2*)x)[i];
        ((__half2*)g_h16)[i] = __floats2half2_rn(v.x, v.y);
    }
}

// ---------------- weight transpose + tf32 rna rounding ----------------
__global__ void k_wtrans(const float* __restrict__ w1, const float* __restrict__ w2,
                         const float* __restrict__ w3) {
    __shared__ float t[32][33];
    int mi = blockIdx.z;
    const float* src = (mi < 3) ? (w1 + (size_t)mi * FD * FD)
                     : (mi < 6) ? (w2 + (size_t)(mi - 3) * FD * FD)
                                : (w3 + (size_t)(mi - 6) * FD * FD);
    float* dst = g_wt + (size_t)mi * FD * FD;
    int x0 = blockIdx.x * 32, y0 = blockIdx.y * 32;
    for (int dy = threadIdx.y; dy < 32; dy += 8)
        t[dy][threadIdx.x] = src[(size_t)(y0 + dy) * FD + x0 + threadIdx.x];
    __syncthreads();
    for (int dy = threadIdx.y; dy < 32; dy += 8)
        dst[(size_t)(x0 + dy) * FD + y0 + threadIdx.x] = f2tf32f(t[threadIdx.x][dy]);
}

// ---------------- aggregation + GIN combine from fp16, tf32-rounded fp32 out ----------------
__global__ void __launch_bounds__(256) k_aggr16(const float* __restrict__ epsp) {
    int node = blockIdx.x * 8 + (threadIdx.x >> 5);
    if (node >= NN) return;
    int lane = threadIdx.x & 31;
    int s = g_rowptr[node], e = g_rowptr[node + 1];
    float alpha = 1.0f + epsp[0];
    const uint2* hp = (const uint2*)g_h16;      // 4 feats per lane, 32 lanes per row
    uint2 hv = hp[(size_t)node * 32 + lane];
    float2 f0 = __half22float2(*(const __half2*)&hv.x);
    float2 f1 = __half22float2(*(const __half2*)&hv.y);
    float4 acc = make_float4(alpha * f0.x, alpha * f0.y, alpha * f1.x, alpha * f1.y);
    int j = s;
    for (; j + 3 < e; j += 4) {
        int s0 = g_srcsorted[j],     s1 = g_srcsorted[j + 1];
        int s2 = g_srcsorted[j + 2], s3 = g_srcsorted[j + 3];
        uint2 v0 = hp[(size_t)s0 * 32 + lane];
        uint2 v1 = hp[(size_t)s1 * 32 + lane];
        uint2 v2 = hp[(size_t)s2 * 32 + lane];
        uint2 v3 = hp[(size_t)s3 * 32 + lane];
        acc_h4(acc, v0); acc_h4(acc, v1); acc_h4(acc, v2); acc_h4(acc, v3);
    }
    for (; j < e; j++) acc_h4(acc, hp[(size_t)g_srcsorted[j] * 32 + lane]);
    acc.x = f2tf32f(acc.x); acc.y = f2tf32f(acc.y);
    acc.z = f2tf32f(acc.z); acc.w = f2tf32f(acc.w);
    ((float4*)g_aggr)[(size_t)node * 32 + lane] = acc;
}

// ---------------- tf32 mma GEMM, cp.async double-buffered ----------------
// mode 0: C = acc + bias (raw).  mode 1: C = rna(relu(acc + bias)).
__global__ void __launch_bounds__(256) k_gemm_cp(
    const float* __restrict__ A,
    const float* __restrict__ Wt, const float* __restrict__ bias,
    float* __restrict__ C, int M, int mode)
{
    extern __shared__ float smem[];
    uint32_t sb = smem_u32(smem);

    int tid = threadIdx.x;
    int w = tid >> 5, lane = tid & 31;
    int m0 = blockIdx.x * 128;

    auto stage = [&](int c, int buf) {
        uint32_t base = sb + (uint32_t)buf * (BUFSZ * 4);
#pragma unroll
        for (int i = 0; i < 8; i++) {
            int o = i * 256 + tid;
            int row = (o & 1023) >> 3;
            int q = o & 7;
            uint32_t dst = base + (uint32_t)((o >> 10) * (ABUF * 4) + row * (PIT * 4) + q * 16);
            if (o < 1024) {
                int m = m0 + row;
                cp16(dst, A + ((m < M) ? ((size_t)m * FD + c * BK + q * 4)
                                       : ((size_t)c * BK + q * 4)));
            } else {
                cp16(dst, Wt + (size_t)row * FD + c * BK + q * 4);
            }
        }
        asm volatile("cp.async.commit_group;" ::: "memory");
    };

    stage(0, 0);

    int warpM = w >> 2, warpN = w & 3;
    int g = lane >> 2, t = lane & 3;

    float c[4][4][4];
#pragma unroll
    for (int ma = 0; ma < 4; ma++)
#pragma unroll
        for (int nb = 0; nb < 4; nb++)
#pragma unroll
            for (int r = 0; r < 4; r++) c[ma][nb][r] = 0.f;

#pragma unroll
    for (int ch = 0; ch < 4; ch++) {
        if (ch < 3) stage(ch + 1, (ch + 1) & 1);
        if (ch < 3)
            asm volatile("cp.async.wait_group 1;" ::: "memory");
        else
            asm volatile("cp.async.wait_group 0;" ::: "memory");
        __syncthreads();

        const uint32_t* As = (const uint32_t*)(smem + (ch & 1) * BUFSZ);
        const uint32_t* Bs = As + ABUF;
#pragma unroll
        for (int ks = 0; ks < 4; ks++) {
            int k0 = ks * 8;
            uint32_t af[4][4];
#pragma unroll
            for (int ma = 0; ma < 4; ma++) {
                int r = warpM * 64 + ma * 16 + g;
                const uint32_t* ap = As + r * PIT + k0 + t;
                af[ma][0] = ap[0];
                af[ma][1] = ap[8 * PIT];
                af[ma][2] = ap[4];
                af[ma][3] = ap[8 * PIT + 4];
            }
            uint32_t bf[4][2];
#pragma unroll
            for (int nb = 0; nb < 4; nb++) {
                int n = warpN * 32 + nb * 8 + g;
                const uint32_t* bp = Bs + n * PIT + k0 + t;
                bf[nb][0] = bp[0];
                bf[nb][1] = bp[4];
            }
#pragma unroll
            for (int ma = 0; ma < 4; ma++)
#pragma unroll
                for (int nb = 0; nb < 4; nb++)
                    mma_tf32(c[ma][nb], af[ma], bf[nb]);
        }
        __syncthreads();
    }

#pragma unroll
    for (int ma = 0; ma < 4; ma++) {
        int r0 = m0 + warpM * 64 + ma * 16 + g;
#pragma unroll
        for (int nb = 0; nb < 4; nb++) {
            int cn = warpN * 32 + nb * 8 + 2 * t;
            float b0 = bias[cn], b1 = bias[cn + 1];
            float o0 = c[ma][nb][0] + b0, o1 = c[ma][nb][1] + b1;
            float o2 = c[ma][nb][2] + b0, o3 = c[ma][nb][3] + b1;
            if (mode) {
                o0 = f2tf32f(fmaxf(o0, 0.f)); o1 = f2tf32f(fmaxf(o1, 0.f));
                o2 = f2tf32f(fmaxf(o2, 0.f)); o3 = f2tf32f(fmaxf(o3, 0.f));
            }
            if (r0 < M)     *(float2*)&C[(size_t)r0 * FD + cn]       = make_float2(o0, o1);
            if (r0 + 8 < M) *(float2*)&C[(size_t)(r0 + 8) * FD + cn] = make_float2(o2, o3);
        }
    }
}

// ---------------- proj GEMM fused with pool partial-sums ----------------
__global__ void __launch_bounds__(256) k_gemm_proj(
    const float* __restrict__ A,
    const float* __restrict__ Wt, const float* __restrict__ bias,
    const int* __restrict__ batch, float* __restrict__ poolp, int M)
{
    extern __shared__ float smem[];
    uint32_t sb = smem_u32(smem);
    int* sbatch = (int*)(smem + R0FL);

    int tid = threadIdx.x;
    int w = tid >> 5, lane = tid & 31;
    int m0 = blockIdx.x * 128;

    auto stage = [&](int c, int buf) {
        uint32_t base = sb + (uint32_t)buf * (BUFSZ * 4);
#pragma unroll
        for (int i = 0; i < 8; i++) {
            int o = i * 256 + tid;
            int row = (o & 1023) >> 3;
            int q = o & 7;
            uint32_t dst = base + (uint32_t)((o >> 10) * (ABUF * 4) + row * (PIT * 4) + q * 16);
            if (o < 1024) {
                int m = m0 + row;
                cp16(dst, A + ((m < M) ? ((size_t)m * FD + c * BK + q * 4)
                                       : ((size_t)c * BK + q * 4)));
            } else {
                cp16(dst, Wt + (size_t)row * FD + c * BK + q * 4);
            }
        }
        asm volatile("cp.async.commit_group;" ::: "memory");
    };

    stage(0, 0);

    int warpM = w >> 2, warpN = w & 3;
    int g = lane >> 2, t = lane & 3;

    float c[4][4][4];
#pragma unroll
    for (int ma = 0; ma < 4; ma++)
#pragma unroll
        for (int nb = 0; nb < 4; nb++)
#pragma unroll
            for (int r = 0; r < 4; r++) c[ma][nb][r] = 0.f;

#pragma unroll
    for (int ch = 0; ch < 4; ch++) {
        if (ch < 3) stage(ch + 1, (ch + 1) & 1);
        if (ch < 3)
            asm volatile("cp.async.wait_group 1;" ::: "memory");
        else
            asm volatile("cp.async.wait_group 0;" ::: "memory");
        __syncthreads();

        const uint32_t* As = (const uint32_t*)(smem + (ch & 1) * BUFSZ);
        const uint32_t* Bs = As + ABUF;
#pragma unroll
        for (int ks = 0; ks < 4; ks++) {
            int k0 = ks * 8;
            uint32_t af[4][4];
#pragma unroll
            for (int ma = 0; ma < 4; ma++) {
                int r = warpM * 64 + ma * 16 + g;
                const uint32_t* ap = As + r * PIT + k0 + t;
                af[ma][0] = ap[0];
                af[ma][1] = ap[8 * PIT];
                af[ma][2] = ap[4];
                af[ma][3] = ap[8 * PIT + 4];
            }
            uint32_t bf[4][2];
#pragma unroll
            for (int nb = 0; nb < 4; nb++) {
                int n = warpN * 32 + nb * 8 + g;
                const uint32_t* bp = Bs + n * PIT + k0 + t;
                bf[nb][0] = bp[0];
                bf[nb][1] = bp[4];
            }
#pragma unroll
            for (int ma = 0; ma < 4; ma++)
#pragma unroll
                for (int nb = 0; nb < 4; nb++)
                    mma_tf32(c[ma][nb], af[ma], bf[nb]);
        }
        __syncthreads();
    }

    // T = relu(acc + b1) into SMEM [128][TPIT]; batch ids alongside
    if (tid < 128) sbatch[tid] = (m0 + tid < M) ? batch[m0 + tid] : -1;
#pragma unroll
    for (int ma = 0; ma < 4; ma++) {
        int r0 = warpM * 64 + ma * 16 + g;
#pragma unroll
        for (int nb = 0; nb < 4; nb++) {
            int cn = warpN * 32 + nb * 8 + 2 * t;
            float b0 = bias[cn], b1v = bias[cn + 1];
            smem[r0 * TPIT + cn]           = fmaxf(c[ma][nb][0] + b0, 0.f);
            smem[r0 * TPIT + cn + 1]       = fmaxf(c[ma][nb][1] + b1v, 0.f);
            smem[(r0 + 8) * TPIT + cn]     = fmaxf(c[ma][nb][2] + b0, 0.f);
            smem[(r0 + 8) * TPIT + cn + 1] = fmaxf(c[ma][nb][3] + b1v, 0.f);
        }
    }
    __syncthreads();

    // segmented column sums over sorted batch ids
    {
        int f = tid & 127;
        int half = tid >> 7;
        int base = half * 64;
        if (m0 + base < M) {
            float acc = 0.f;
            int curg = sbatch[base];
            for (int i = 0; i < 64; i++) {
                int gi = sbatch[base + i];
                if (gi < 0) break;
                if (gi != curg) {
                    atomicAdd(&poolp[(size_t)curg * FD + f], acc);
                    acc = 0.f;
                    curg = gi;
                }
                acc += smem[(base + i) * TPIT + f];
            }
            if (curg >= 0) atomicAdd(&poolp[(size_t)curg * FD + f], acc);
        }
    }
}

// ---------------- GraphNorm (+relu), 2-pass; writes fp32 (rna) + fp16 ----------------
__global__ void __launch_bounds__(128) k_gnorm(
    float* __restrict__ h,
    const float* __restrict__ scale, const float* __restrict__ weight,
    const float* __restrict__ bias)
{
    int g = blockIdx.x;
    int f = threadIdx.x;
    int s = g_gstart[g], e = g_gstart[g + 1];
    float cnt = fmaxf((float)(e - s), 1.0f);

    float sum = 0.f, sq = 0.f;
#pragma unroll 4
    for (int i = s; i < e; i++) {
        float v = h[(size_t)i * FD + f];
        sum += v;
        sq += v * v;
    }
    float mean = sum / cnt;
    float ms = mean * scale[f];
    float var = sq / cnt - 2.f * ms * mean + ms * ms;
    float inv = weight[f] * rsqrtf(var + 1e-8f);
    float bf = bias[f];

#pragma unroll 4
    for (int i = s; i < e; i++) {
        float o = f2tf32f(fmaxf(inv * (h[(size_t)i * FD + f] - ms) + bf, 0.f));
        h[(size_t)i * FD + f] = o;
        g_h16[(size_t)i * FD + f] = __float2half(o);
    }
}

// ---------------- final tiny GEMM: out[g, lofs+f] = pool[g]@W2 + cnt*b2 ----------------
__global__ void __launch_bounds__(128) k_pool2(
    const float* __restrict__ poolp,
    const float* __restrict__ w2, const float* __restrict__ b2,
    float* __restrict__ out, int lofs)
{
    __shared__ float sp[128];
    int g = blockIdx.x;
    int f = threadIdx.x;
    sp[f] = poolp[(size_t)g * FD + f];
    __syncthreads();
    if (f < TG) {
        int cnt = g_gstart[g + 1] - g_gstart[g];
        float o = (float)cnt * b2[f];
#pragma unroll 8
        for (int k = 0; k < FD; k++) o += sp[k] * w2[k * TG + f];
        out[(size_t)g * (LL * TG) + lofs + f] = o;
    }
}

// ---------------- launcher ----------------
extern "C" void kernel_launch(void* const* d_in, const int* in_sizes, int n_in,
                              void* d_out, int out_size) {
    const float* x        = (const float*)d_in[0];
    const int*   edge     = (const int*)d_in[1];
    const int*   batch    = (const int*)d_in[2];
    const float* conv_w1  = (const float*)d_in[3];
    const float* conv_b1  = (const float*)d_in[4];
    const float* conv_w2  = (const float*)d_in[5];
    const float* conv_b2  = (const float*)d_in[6];
    const float* eps      = (const float*)d_in[7];
    const float* gn_scale = (const float*)d_in[8];
    const float* gn_weight= (const float*)d_in[9];
    const float* gn_bias  = (const float*)d_in[10];
    const float* proj_w1  = (const float*)d_in[11];
    const float* proj_b1  = (const float*)d_in[12];
    const float* proj_w2  = (const float*)d_in[13];
    const float* proj_b2  = (const float*)d_in[14];
    float* out = (float*)d_out;

    const int* src = edge;
    const int* dst = edge + EE;

    float *p_h, *p_aggr, *p_t, *p_wt, *p_pool;
    cudaGetSymbolAddress((void**)&p_h, g_h);
    cudaGetSymbolAddress((void**)&p_aggr, g_aggr);
    cudaGetSymbolAddress((void**)&p_t, g_t);
    cudaGetSymbolAddress((void**)&p_wt, g_wt);
    cudaGetSymbolAddress((void**)&p_pool, g_pool);

    cudaFuncSetAttribute(k_gemm_cp, cudaFuncAttributeMaxDynamicSharedMemorySize, GEMM_SMEM);
    cudaFuncSetAttribute(k_gemm_proj, cudaFuncAttributeMaxDynamicSharedMemorySize, GEMM_SMEM);

    // init + CSR build + graph starts + weight transpose + x->fp16
    k_init_zero<<<(LL * GG * FD + 255) / 256, 256>>>();
    k_hist<<<(EE + 255) / 256, 256>>>(dst);
    k_scan1<<<NB, 1024>>>();
    k_scan2<<<1, 128>>>();
    k_scan3<<<NB, 1024>>>();
    k_copycur<<<(NN + 255) / 256, 256>>>();
    k_bucket<<<(EE + 255) / 256, 256>>>(src, dst);
    k_gstart<<<3, 256>>>(batch);
    k_wtrans<<<dim3(4, 4, 9), dim3(32, 8)>>>(conv_w1, conv_w2, proj_w1);
    k_x16<<<(NN * FD / 2 + 255) / 256, 256>>>(x);

    for (int l = 0; l < LL; l++) {
        // aggr = rna((1+eps)h + sum_j h_j), gathered from fp16 copy
        k_aggr16<<<(NN + 7) / 8, 256>>>(eps + l);
        // t = rna(relu(aggr @ W1 + b1))
        k_gemm_cp<<<MTILES, 256, GEMM_SMEM>>>(p_aggr,
                                              p_wt + (size_t)l * FD * FD,
                                              conv_b1 + (size_t)l * FD, p_t, NN, 1);
        // h = t @ W2 + b2
        k_gemm_cp<<<MTILES, 256, GEMM_SMEM>>>(p_t,
                                              p_wt + (size_t)(3 + l) * FD * FD,
                                              conv_b2 + (size_t)l * FD, p_h, NN, 0);
        // GraphNorm + relu + rna; also refresh fp16 copy
        k_gnorm<<<GG, 128>>>(p_h, gn_scale + (size_t)l * FD,
                             gn_weight + (size_t)l * FD, gn_bias + (size_t)l * FD);
        // pool_l += segsum(relu(h @ W1p + b1p))
        k_gemm_proj<<<MTILES, 256, GEMM_SMEM>>>(p_h,
                                                p_wt + (size_t)(6 + l) * FD * FD,
                                                proj_b1 + (size_t)l * FD,
                                                batch, p_pool + (size_t)l * GG * FD, NN);
        // out_l = pool_l @ W2p + cnt*b2p
        k_pool2<<<GG, 128>>>(p_pool + (size_t)l * GG * FD,
                             proj_w2 + (size_t)l * FD * TG,
                             proj_b2 + (size_t)l * TG, out, l * TG);
    }
}

// round 9
// speedup vs baseline: 1.7522x; 1.5394x over previous
#include <cuda_runtime.h>
#include <cuda_fp16.h>
#include <cstdint>

#define NN 100000
#define EE 1600000
#define FD 128
#define GG 512
#define LL 3
#define TG 64
#define NB ((NN + 1023) / 1024)   /* 98 scan blocks */
#define MTILES ((NN + 127) / 128) /* 782 */

#define PH 136                     /* halves per SMEM row; (4*row+t)%32 conflict-free */
#define PHB (PH * 2)               /* 272 bytes per row */
#define TILE_B (128 * PHB)         /* 34816 B per operand tile */
#define GEMM_SMEM (2 * TILE_B)     /* 69632 B */
#define TPIT 132                   /* fp32 pitch for proj T tile */
#define PROJ_SMEM (GEMM_SMEM + 512)

// ---------------- device scratch (no allocs allowed) ----------------
__device__ float  g_h[(size_t)NN * FD];       // fp32 conv2 output (gnorm input)
__device__ __half g_h16[(size_t)NN * FD];     // fp16 activations (gather/proj source)
__device__ __half g_aggr16[(size_t)NN * FD];
__device__ __half g_t16[(size_t)NN * FD];
__device__ __half g_wt16[9 * FD * FD];        // pre-transposed weights [n][k], fp16
__device__ float  g_pool[LL * GG * FD];
__device__ int    g_deg[NN];
__device__ int    g_rowptr[NN + 1];
__device__ int    g_cursor[NN];
__device__ int    g_bsum[NB];
__device__ int    g_boff[NB];
__device__ int    g_srcsorted[EE];
__device__ int    g_gstart[GG + 1];

__device__ __forceinline__ uint32_t smem_u32(const void* p) {
    uint32_t a;
    asm("{ .reg .u64 t; cvta.to.shared.u64 t, %1; cvt.u32.u64 %0, t; }" : "=r"(a) : "l"(p));
    return a;
}
__device__ __forceinline__ void cp16(uint32_t dst, const void* src) {
    asm volatile("cp.async.cg.shared.global [%0], [%1], 16;"
                 :: "r"(dst), "l"(src) : "memory");
}
__device__ __forceinline__ void mma_f16(float* c, const uint32_t* a, const uint32_t* b) {
    asm volatile(
        "mma.sync.aligned.m16n8k16.row.col.f32.f16.f16.f32 "
        "{%0,%1,%2,%3}, {%4,%5,%6,%7}, {%8,%9}, {%0,%1,%2,%3};"
        : "+f"(c[0]), "+f"(c[1]), "+f"(c[2]), "+f"(c[3])
        : "r"(a[0]), "r"(a[1]), "r"(a[2]), "r"(a[3]), "r"(b[0]), "r"(b[1]));
}
__device__ __forceinline__ void acc_h4(float4& acc, uint2 v) {
    float2 f0 = __half22float2(*(const __half2*)&v.x);
    float2 f1 = __half22float2(*(const __half2*)&v.y);
    acc.x += f0.x; acc.y += f0.y; acc.z += f1.x; acc.w += f1.y;
}

// ---------------- init / CSR build ----------------
__global__ void k_init_zero() {
    int i = blockIdx.x * 256 + threadIdx.x;
    if (i < NN) g_deg[i] = 0;
    if (i < LL * GG * FD) g_pool[i] = 0.f;
}
__global__ void k_hist(const int* __restrict__ dst) {
    int e = blockIdx.x * 256 + threadIdx.x;
    if (e < EE) atomicAdd(&g_deg[dst[e]], 1);
}
__global__ void k_scan1() {
    __shared__ int sh[1024];
    int i = blockIdx.x * 1024 + threadIdx.x;
    int v = (i < NN) ? g_deg[i] : 0;
    sh[threadIdx.x] = v;
    __syncthreads();
    for (int off = 1; off < 1024; off <<= 1) {
        int t = sh[threadIdx.x];
        int a = (threadIdx.x >= off) ? sh[threadIdx.x - off] : 0;
        __syncthreads();
        sh[threadIdx.x] = t + a;
        __syncthreads();
    }
    if (i < NN) g_rowptr[i + 1] = sh[threadIdx.x];
    if (threadIdx.x == 1023) g_bsum[blockIdx.x] = sh[1023];
}
__global__ void k_scan2() {
    __shared__ int sh[128];
    int t = threadIdx.x;
    int v = (t < NB) ? g_bsum[t] : 0;
    sh[t] = v;
    __syncthreads();
    for (int off = 1; off < 128; off <<= 1) {
        int x = sh[t];
        int a = (t >= off) ? sh[t - off] : 0;
        __syncthreads();
        sh[t] = x + a;
        __syncthreads();
    }
    if (t < NB) g_boff[t] = sh[t] - v;
}
__global__ void k_scan3() {
    int i = blockIdx.x * 1024 + threadIdx.x;
    if (i < NN) g_rowptr[i + 1] += g_boff[blockIdx.x];
    if (i == 0) g_rowptr[0] = 0;
}
__global__ void k_copycur() {
    int i = blockIdx.x * 256 + threadIdx.x;
    if (i < NN) g_cursor[i] = g_rowptr[i];
}
__global__ void k_bucket(const int* __restrict__ src, const int* __restrict__ dst) {
    int e = blockIdx.x * 256 + threadIdx.x;
    if (e < EE) {
        int d = dst[e];
        int pos = atomicAdd(&g_cursor[d], 1);
        g_srcsorted[pos] = src[e];
    }
}
__global__ void k_gstart(const int* __restrict__ batch) {
    int g = blockIdx.x * 256 + threadIdx.x;
    if (g <= GG) {
        int lo = 0, hi = NN;
        while (lo < hi) {
            int mid = (lo + hi) >> 1;
            if (batch[mid] < g) lo = mid + 1; else hi = mid;
        }
        g_gstart[g] = lo;
    }
}

// ---------------- x -> fp16 ----------------
__global__ void k_x16(const float* __restrict__ x) {
    int i = blockIdx.x * 256 + threadIdx.x;
    if (i < NN * FD / 2) {
        float2 v = ((const float2*)x)[i];
        ((__half2*)g_h16)[i] = __floats2half2_rn(v.x, v.y);
    }
}

// ---------------- weight transpose -> fp16 [n][k] ----------------
__global__ void k_wtrans(const float* __restrict__ w1, const float* __restrict__ w2,
                         const float* __restrict__ w3) {
    __shared__ float t[32][33];
    int mi = blockIdx.z;
    const float* src = (mi < 3) ? (w1 + (size_t)mi * FD * FD)
                     : (mi < 6) ? (w2 + (size_t)(mi - 3) * FD * FD)
                                : (w3 + (size_t)(mi - 6) * FD * FD);
    __half* dst = g_wt16 + (size_t)mi * FD * FD;
    int x0 = blockIdx.x * 32, y0 = blockIdx.y * 32;
    for (int dy = threadIdx.y; dy < 32; dy += 8)
        t[dy][threadIdx.x] = src[(size_t)(y0 + dy) * FD + x0 + threadIdx.x];
    __syncthreads();
    for (int dy = threadIdx.y; dy < 32; dy += 8)
        dst[(size_t)(x0 + dy) * FD + y0 + threadIdx.x] = __float2half(t[threadIdx.x][dy]);
}

// ---------------- aggregation + GIN combine (fp16 in, fp16 out) ----------------
__global__ void __launch_bounds__(256) k_aggr16(const float* __restrict__ epsp) {
    int node = blockIdx.x * 8 + (threadIdx.x >> 5);
    if (node >= NN) return;
    int lane = threadIdx.x & 31;
    int s = g_rowptr[node], e = g_rowptr[node + 1];
    float alpha = 1.0f + epsp[0];
    const uint2* hp = (const uint2*)g_h16;
    uint2 hv = hp[(size_t)node * 32 + lane];
    float2 f0 = __half22float2(*(const __half2*)&hv.x);
    float2 f1 = __half22float2(*(const __half2*)&hv.y);
    float4 acc = make_float4(alpha * f0.x, alpha * f0.y, alpha * f1.x, alpha * f1.y);
    int j = s;
    for (; j + 3 < e; j += 4) {
        int s0 = g_srcsorted[j],     s1 = g_srcsorted[j + 1];
        int s2 = g_srcsorted[j + 2], s3 = g_srcsorted[j + 3];
        uint2 v0 = hp[(size_t)s0 * 32 + lane];
        uint2 v1 = hp[(size_t)s1 * 32 + lane];
        uint2 v2 = hp[(size_t)s2 * 32 + lane];
        uint2 v3 = hp[(size_t)s3 * 32 + lane];
        acc_h4(acc, v0); acc_h4(acc, v1); acc_h4(acc, v2); acc_h4(acc, v3);
    }
    for (; j < e; j++) acc_h4(acc, hp[(size_t)g_srcsorted[j] * 32 + lane]);
    uint2 o;
    *(__half2*)&o.x = __floats2half2_rn(acc.x, acc.y);
    *(__half2*)&o.y = __floats2half2_rn(acc.z, acc.w);
    ((uint2*)g_aggr16)[(size_t)node * 32 + lane] = o;
}

// ---------------- fp16 mma GEMM, single-stage full-K tiles ----------------
// out16 != 0: C16 = fp16(relu(acc+bias)).  out16 == 0: C32 = acc+bias (fp32).
__global__ void __launch_bounds__(256) k_gemm16(
    const __half* __restrict__ A16, const __half* __restrict__ Wt16,
    const float* __restrict__ bias,
    __half* __restrict__ C16, float* __restrict__ C32, int M, int out16)
{
    extern __shared__ __half smem[];
    uint32_t sb = smem_u32(smem);
    int tid = threadIdx.x;
    int w = tid >> 5, lane = tid & 31;
    int m0 = blockIdx.x * 128;

    // stage A (side 0) + B (side 1): 4096 x 16B
#pragma unroll
    for (int i = 0; i < 16; i++) {
        int o = i * 256 + tid;
        int side = o >> 11;
        int idx = o & 2047;
        int row = idx >> 4;
        int q = idx & 15;
        uint32_t dst = sb + (uint32_t)(side * TILE_B + row * PHB + q * 16);
        if (side == 0) {
            int m = m0 + row;
            cp16(dst, A16 + ((m < M) ? ((size_t)m * FD + q * 8) : (size_t)(q * 8)));
        } else {
            cp16(dst, Wt16 + (size_t)row * FD + q * 8);
        }
    }
    asm volatile("cp.async.commit_group;" ::: "memory");
    asm volatile("cp.async.wait_group 0;" ::: "memory");
    __syncthreads();

    int warpM = w >> 2, warpN = w & 3;
    int g = lane >> 2, t = lane & 3;

    const uint32_t* As = (const uint32_t*)smem;              // pitch 68 u32
    const uint32_t* Bs = (const uint32_t*)(smem + 128 * PH);

    float c[4][4][4];
#pragma unroll
    for (int ma = 0; ma < 4; ma++)
#pragma unroll
        for (int nb = 0; nb < 4; nb++)
#pragma unroll
            for (int r = 0; r < 4; r++) c[ma][nb][r] = 0.f;

#pragma unroll
    for (int ks = 0; ks < 8; ks++) {
        int kq = ks * 8;      // u32 offset for k0 = ks*16
        uint32_t af[4][4];
#pragma unroll
        for (int ma = 0; ma < 4; ma++) {
            int r = warpM * 64 + ma * 16 + g;
            const uint32_t* ap = As + r * 68 + kq + t;
            af[ma][0] = ap[0];
            af[ma][1] = ap[8 * 68];
            af[ma][2] = ap[4];
            af[ma][3] = ap[8 * 68 + 4];
        }
        uint32_t bf[4][2];
#pragma unroll
        for (int nb = 0; nb < 4; nb++) {
            int n = warpN * 32 + nb * 8 + g;
            const uint32_t* bp = Bs + n * 68 + kq + t;
            bf[nb][0] = bp[0];
            bf[nb][1] = bp[4];
        }
#pragma unroll
        for (int ma = 0; ma < 4; ma++)
#pragma unroll
            for (int nb = 0; nb < 4; nb++)
                mma_f16(c[ma][nb], af[ma], bf[nb]);
    }

#pragma unroll
    for (int ma = 0; ma < 4; ma++) {
        int r0 = m0 + warpM * 64 + ma * 16 + g;
#pragma unroll
        for (int nb = 0; nb < 4; nb++) {
            int cn = warpN * 32 + nb * 8 + 2 * t;
            float b0 = bias[cn], b1 = bias[cn + 1];
            float o0 = c[ma][nb][0] + b0, o1 = c[ma][nb][1] + b1;
            float o2 = c[ma][nb][2] + b0, o3 = c[ma][nb][3] + b1;
            if (out16) {
                uint32_t p0, p1;
                *(__half2*)&p0 = __floats2half2_rn(fmaxf(o0, 0.f), fmaxf(o1, 0.f));
                *(__half2*)&p1 = __floats2half2_rn(fmaxf(o2, 0.f), fmaxf(o3, 0.f));
                if (r0 < M)     ((uint32_t*)C16)[(size_t)r0 * 64 + (cn >> 1)]       = p0;
                if (r0 + 8 < M) ((uint32_t*)C16)[(size_t)(r0 + 8) * 64 + (cn >> 1)] = p1;
            } else {
                if (r0 < M)     *(float2*)&C32[(size_t)r0 * FD + cn]       = make_float2(o0, o1);
                if (r0 + 8 < M) *(float2*)&C32[(size_t)(r0 + 8) * FD + cn] = make_float2(o2, o3);
            }
        }
    }
}

// ---------------- proj GEMM (fp16) fused with pool partial-sums ----------------
__global__ void __launch_bounds__(256) k_gemm_proj16(
    const __half* __restrict__ A16, const __half* __restrict__ Wt16,
    const float* __restrict__ bias,
    const int* __restrict__ batch, float* __restrict__ poolp, int M)
{
    extern __shared__ __half smem[];
    uint32_t sb = smem_u32(smem);
    float* Tt = (float*)smem;                         // T tile overwrites operands
    int* sbatch = (int*)((char*)smem + GEMM_SMEM);
    int tid = threadIdx.x;
    int w = tid >> 5, lane = tid & 31;
    int m0 = blockIdx.x * 128;

#pragma unroll
    for (int i = 0; i < 16; i++) {
        int o = i * 256 + tid;
        int side = o >> 11;
        int idx = o & 2047;
        int row = idx >> 4;
        int q = idx & 15;
        uint32_t dst = sb + (uint32_t)(side * TILE_B + row * PHB + q * 16);
        if (side == 0) {
            int m = m0 + row;
            cp16(dst, A16 + ((m < M) ? ((size_t)m * FD + q * 8) : (size_t)(q * 8)));
        } else {
            cp16(dst, Wt16 + (size_t)row * FD + q * 8);
        }
    }
    asm volatile("cp.async.commit_group;" ::: "memory");
    asm volatile("cp.async.wait_group 0;" ::: "memory");
    __syncthreads();

    int warpM = w >> 2, warpN = w & 3;
    int g = lane >> 2, t = lane & 3;

    const uint32_t* As = (const uint32_t*)smem;
    const uint32_t* Bs = (const uint32_t*)(smem + 128 * PH);

    float c[4][4][4];
#pragma unroll
    for (int ma = 0; ma < 4; ma++)
#pragma unroll
        for (int nb = 0; nb < 4; nb++)
#pragma unroll
            for (int r = 0; r < 4; r++) c[ma][nb][r] = 0.f;

#pragma unroll
    for (int ks = 0; ks < 8; ks++) {
        int kq = ks * 8;
        uint32_t af[4][4];
#pragma unroll
        for (int ma = 0; ma < 4; ma++) {
            int r = warpM * 64 + ma * 16 + g;
            const uint32_t* ap = As + r * 68 + kq + t;
            af[ma][0] = ap[0];
            af[ma][1] = ap[8 * 68];
            af[ma][2] = ap[4];
            af[ma][3] = ap[8 * 68 + 4];
        }
        uint32_t bf[4][2];
#pragma unroll
        for (int nb = 0; nb < 4; nb++) {
            int n = warpN * 32 + nb * 8 + g;
            const uint32_t* bp = Bs + n * 68 + kq + t;
            bf[nb][0] = bp[0];
            bf[nb][1] = bp[4];
        }
#pragma unroll
        for (int ma = 0; ma < 4; ma++)
#pragma unroll
            for (int nb = 0; nb < 4; nb++)
                mma_f16(c[ma][nb], af[ma], bf[nb]);
    }
    __syncthreads();   // operands dead; reuse SMEM for T tile

    if (tid < 128) sbatch[tid] = (m0 + tid < M) ? batch[m0 + tid] : -1;
#pragma unroll
    for (int ma = 0; ma < 4; ma++) {
        int r0 = warpM * 64 + ma * 16 + g;
#pragma unroll
        for (int nb = 0; nb < 4; nb++) {
            int cn = warpN * 32 + nb * 8 + 2 * t;
            float b0 = bias[cn], b1v = bias[cn + 1];
            Tt[r0 * TPIT + cn]           = fmaxf(c[ma][nb][0] + b0, 0.f);
            Tt[r0 * TPIT + cn + 1]       = fmaxf(c[ma][nb][1] + b1v, 0.f);
            Tt[(r0 + 8) * TPIT + cn]     = fmaxf(c[ma][nb][2] + b0, 0.f);
            Tt[(r0 + 8) * TPIT + cn + 1] = fmaxf(c[ma][nb][3] + b1v, 0.f);
        }
    }
    __syncthreads();

    // segmented column sums over sorted batch ids
    {
        int f = tid & 127;
        int half = tid >> 7;
        int base = half * 64;
        if (m0 + base < M) {
            float acc = 0.f;
            int curg = sbatch[base];
            for (int i = 0; i < 64; i++) {
                int gi = sbatch[base + i];
                if (gi < 0) break;
                if (gi != curg) {
                    atomicAdd(&poolp[(size_t)curg * FD + f], acc);
                    acc = 0.f;
                    curg = gi;
                }
                acc += Tt[(base + i) * TPIT + f];
            }
            if (curg >= 0) atomicAdd(&poolp[(size_t)curg * FD + f], acc);
        }
    }
}

// ---------------- GraphNorm (+relu): fp32 in, fp16 out ----------------
__global__ void __launch_bounds__(128) k_gnorm(
    const float* __restrict__ h,
    const float* __restrict__ scale, const float* __restrict__ weight,
    const float* __restrict__ bias)
{
    int g = blockIdx.x;
    int f = threadIdx.x;
    int s = g_gstart[g], e = g_gstart[g + 1];
    float cnt = fmaxf((float)(e - s), 1.0f);

    float sum = 0.f, sq = 0.f;
#pragma unroll 4
    for (int i = s; i < e; i++) {
        float v = h[(size_t)i * FD + f];
        sum += v;
        sq += v * v;
    }
    float mean = sum / cnt;
    float ms = mean * scale[f];
    float var = sq / cnt - 2.f * ms * mean + ms * ms;
    float inv = weight[f] * rsqrtf(var + 1e-8f);
    float bf = bias[f];

#pragma unroll 4
    for (int i = s; i < e; i++) {
        float o = fmaxf(inv * (h[(size_t)i * FD + f] - ms) + bf, 0.f);
        g_h16[(size_t)i * FD + f] = __float2half(o);
    }
}

// ---------------- final tiny GEMM: out[g, lofs+f] = pool[g]@W2 + cnt*b2 ----------------
__global__ void __launch_bounds__(128) k_pool2(
    const float* __restrict__ poolp,
    const float* __restrict__ w2, const float* __restrict__ b2,
    float* __restrict__ out, int lofs)
{
    __shared__ float sp[128];
    int g = blockIdx.x;
    int f = threadIdx.x;
    sp[f] = poolp[(size_t)g * FD + f];
    __syncthreads();
    if (f < TG) {
        int cnt = g_gstart[g + 1] - g_gstart[g];
        float o = (float)cnt * b2[f];
#pragma unroll 8
        for (int k = 0; k < FD; k++) o += sp[k] * w2[k * TG + f];
        out[(size_t)g * (LL * TG) + lofs + f] = o;
    }
}

// ---------------- launcher ----------------
extern "C" void kernel_launch(void* const* d_in, const int* in_sizes, int n_in,
                              void* d_out, int out_size) {
    const float* x        = (const float*)d_in[0];
    const int*   edge     = (const int*)d_in[1];
    const int*   batch    = (const int*)d_in[2];
    const float* conv_w1  = (const float*)d_in[3];
    const float* conv_b1  = (const float*)d_in[4];
    const float* conv_w2  = (const float*)d_in[5];
    const float* conv_b2  = (const float*)d_in[6];
    const float* eps      = (const float*)d_in[7];
    const float* gn_scale = (const float*)d_in[8];
    const float* gn_weight= (const float*)d_in[9];
    const float* gn_bias  = (const float*)d_in[10];
    const float* proj_w1  = (const float*)d_in[11];
    const float* proj_b1  = (const float*)d_in[12];
    const float* proj_w2  = (const float*)d_in[13];
    const float* proj_b2  = (const float*)d_in[14];
    float* out = (float*)d_out;

    const int* src = edge;
    const int* dst = edge + EE;

    float *p_h, *p_pool;
    __half *p_h16, *p_a16, *p_t16, *p_wt16;
    cudaGetSymbolAddress((void**)&p_h, g_h);
    cudaGetSymbolAddress((void**)&p_pool, g_pool);
    cudaGetSymbolAddress((void**)&p_h16, g_h16);
    cudaGetSymbolAddress((void**)&p_a16, g_aggr16);
    cudaGetSymbolAddress((void**)&p_t16, g_t16);
    cudaGetSymbolAddress((void**)&p_wt16, g_wt16);

    cudaFuncSetAttribute(k_gemm16, cudaFuncAttributeMaxDynamicSharedMemorySize, GEMM_SMEM);
    cudaFuncSetAttribute(k_gemm_proj16, cudaFuncAttributeMaxDynamicSharedMemorySize, PROJ_SMEM);

    // init + CSR build + graph starts + weight transpose + x->fp16
    k_init_zero<<<(LL * GG * FD + 255) / 256, 256>>>();
    k_hist<<<(EE + 255) / 256, 256>>>(dst);
    k_scan1<<<NB, 1024>>>();
    k_scan2<<<1, 128>>>();
    k_scan3<<<NB, 1024>>>();
    k_copycur<<<(NN + 255) / 256, 256>>>();
    k_bucket<<<(EE + 255) / 256, 256>>>(src, dst);
    k_gstart<<<3, 256>>>(batch);
    k_wtrans<<<dim3(4, 4, 9), dim3(32, 8)>>>(conv_w1, conv_w2, proj_w1);
    k_x16<<<(NN * FD / 2 + 255) / 256, 256>>>(x);

    for (int l = 0; l < LL; l++) {
        // aggr16 = fp16((1+eps)h + sum_j h_j)
        k_aggr16<<<(NN + 7) / 8, 256>>>(eps + l);
        // t16 = fp16(relu(aggr16 @ W1 + b1))
        k_gemm16<<<MTILES, 256, GEMM_SMEM>>>(p_a16,
                                             p_wt16 + (size_t)l * FD * FD,
                                             conv_b1 + (size_t)l * FD,
                                             p_t16, nullptr, NN, 1);
        // h = t16 @ W2 + b2 (fp32)
        k_gemm16<<<MTILES, 256, GEMM_SMEM>>>(p_t16,
                                             p_wt16 + (size_t)(3 + l) * FD * FD,
                                             conv_b2 + (size_t)l * FD,
                                             nullptr, p_h, NN, 0);
        // GraphNorm + relu -> h16
        k_gnorm<<<GG, 128>>>(p_h, gn_scale + (size_t)l * FD,
                             gn_weight + (size_t)l * FD, gn_bias + (size_t)l * FD);
        // pool_l += segsum(relu(h16 @ W1p + b1p))
        k_gemm_proj16<<<MTILES, 256, PROJ_SMEM>>>(p_h16,
                                                  p_wt16 + (size_t)(6 + l) * FD * FD,
                                                  proj_b1 + (size_t)l * FD,
                                                  batch, p_pool + (size_t)l * GG * FD, NN);
        // out_l = pool_l @ W2p + cnt*b2p
        k_pool2<<<GG, 128>>>(p_pool + (size_t)l * GG * FD,
                             proj_w2 + (size_t)l * FD * TG,
                             proj_b2 + (size_t)l * TG, out, l * TG);
    }
}